// round 16
// baseline (speedup 1.0000x reference)
#include <cuda_runtime.h>
#include <math.h>

#define Bn   8
#define Cn   112
#define Hn   64
#define Wn   64
#define On   112
#define Gn   14
#define K2n  9
#define PGC  378          // 3*G*K2
#define HWn  4096         // 64*64
#define CKn  1008         // C*K2
#define CO_BLK 9          // 378 = 42 * 9

// Scratch (statically allocated: no cudaMalloc allowed)
__device__ float g_pg[(size_t)Bn * PGC * HWn];     // 49.5 MB
__device__ float g_samp[(size_t)Bn * CKn * HWn];   // 132 MB, layout [b][c*9+k][p]

// ---- packed fp32x2 helpers (sm_100+: doubles fp32 FMA throughput) ----------
typedef unsigned long long u64;

__device__ __forceinline__ u64 ffma2(u64 a, u64 b, u64 c) {
    u64 d;
    asm("fma.rn.f32x2 %0, %1, %2, %3;" : "=l"(d) : "l"(a), "l"(b), "l"(c));
    return d;
}
__device__ __forceinline__ u64 add2(u64 a, u64 b) {
    u64 d;
    asm("add.rn.f32x2 %0, %1, %2;" : "=l"(d) : "l"(a), "l"(b));
    return d;
}
__device__ __forceinline__ u64 pack2(float lo, float hi) {
    u64 d;
    asm("mov.b64 %0, {%1, %2};"
        : "=l"(d) : "r"(__float_as_uint(lo)), "r"(__float_as_uint(hi)));
    return d;
}

// ---------------------------------------------------------------------------
// Kernel 1: pg = conv3x3(x, pg_weight) + pg_bias   (stride 1, pad 1)
// v3: 32x32 tile, 8-ci chunks, 2x2 px x 9 co per thread with f32x2-packed
// accumulators (px pair packed). Weights pre-duplicated as float2 in smem so
// each weight read is one LDS.64 feeding an FFMA2 directly. Halo loads use
// division-free row-walk addressing. Slots/FMA: 1.29 -> 0.81.
// ---------------------------------------------------------------------------
__global__ void __launch_bounds__(256) pg_conv_kernel(
    const float* __restrict__ x,
    const float* __restrict__ w,
    const float* __restrict__ bias)
{
    __shared__ __align__(16) float  sx[8][34][34];        // 37.0 KB
    __shared__ __align__(8)  float2 sw2[CO_BLK][8][9];    //  5.1 KB

    const int tid = threadIdx.x;              // 0..255
    const int tx  = tid & 15;                 // pixel-pair col
    const int ty  = tid >> 4;                 // pixel-pair row
    const int tile = blockIdx.x;              // 0..3 (2x2 tiles of 32x32)
    const int gx0 = (tile & 1) << 5;
    const int gy0 = (tile >> 1) << 5;
    const int co0 = blockIdx.y * CO_BLK;      // 42 co-blocks * 9 = 378
    const int b   = blockIdx.z;

    const int lci  = tid >> 5;                // 0..7 : ci this thread loads
    const int lane = tid & 31;

    u64 acc2[2][CO_BLK];
    #pragma unroll
    for (int py = 0; py < 2; py++)
        #pragma unroll
        for (int co = 0; co < CO_BLK; co++) acc2[py][co] = 0ull;

    for (int ci0 = 0; ci0 < Cn; ci0 += 8) {
        // halo load, division-free: thread (lci, lane) walks 34 rows
        {
            const float* src = x + (((size_t)b * Cn + ci0 + lci) * Hn) * Wn;
            const int gxa = gx0 + lane - 1;
            const int gxb = gx0 + 32 + lane - 1;
            for (int yy = 0; yy < 34; yy++) {
                const int gy = gy0 + yy - 1;
                const bool rowok = (unsigned)gy < (unsigned)Hn;
                float v = 0.f;
                if (rowok && (unsigned)gxa < (unsigned)Wn) v = src[gy * Wn + gxa];
                sx[lci][yy][lane] = v;
                if (lane < 2) {
                    float v2 = 0.f;
                    if (rowok && (unsigned)gxb < (unsigned)Wn) v2 = src[gy * Wn + gxb];
                    sx[lci][yy][32 + lane] = v2;
                }
            }
        }
        // weights, duplicated into float2: CO_BLK*8*9 = 648
        for (int i = tid; i < CO_BLK * 72; i += 256) {
            int co = i / 72;
            int r  = i - co * 72;
            int ci = r / 9;
            int kk = r - ci * 9;
            float v = w[((size_t)(co0 + co) * Cn + ci0 + ci) * 9 + kk];
            sw2[co][ci][kk] = make_float2(v, v);
        }
        __syncthreads();

        for (int ci = 0; ci < 8; ci++) {
            // 4x4 window -> packed horizontal pairs (3 shifts x 4 rows)
            u64 xp[4][3];
            #pragma unroll
            for (int yy = 0; yy < 4; yy++) {
                float2 pa = *(const float2*)&sx[ci][ty * 2 + yy][tx * 2];
                float2 pb = *(const float2*)&sx[ci][ty * 2 + yy][tx * 2 + 2];
                xp[yy][0] = pack2(pa.x, pa.y);
                xp[yy][1] = pack2(pa.y, pb.x);
                xp[yy][2] = pack2(pb.x, pb.y);
            }
            #pragma unroll
            for (int kk = 0; kk < 9; kk++) {
                const int ky = kk / 3, kx = kk % 3;
                #pragma unroll
                for (int co = 0; co < CO_BLK; co++) {
                    const u64 wv = *(const u64*)&sw2[co][ci][kk];  // LDS.64 bcast
                    acc2[0][co] = ffma2(xp[0 + ky][kx], wv, acc2[0][co]);
                    acc2[1][co] = ffma2(xp[1 + ky][kx], wv, acc2[1][co]);
                }
            }
        }
        __syncthreads();
    }

    const int ox = gx0 + tx * 2;
    #pragma unroll
    for (int co = 0; co < CO_BLK; co++) {
        const float bv = bias[co0 + co];
        const u64 bv2 = pack2(bv, bv);
        #pragma unroll
        for (int py = 0; py < 2; py++) {
            const int oy = gy0 + ty * 2 + py;
            *(u64*)&g_pg[(((size_t)b * PGC + co0 + co) * Hn + oy) * Wn + ox] =
                add2(acc2[py][co], bv2);
        }
    }
}

// ---------------------------------------------------------------------------
// Kernel 2: deformable bilinear sampling with sigmoid mask (unchanged).
// dy(g,k)=pg[g*18+2k], dx(g,k)=pg[g*18+2k+1], mask(g,k)=sigmoid(pg[252+g*9+k])
// ---------------------------------------------------------------------------
__global__ void __launch_bounds__(256) sample_kernel(const float* __restrict__ x)
{
    const int p  = blockIdx.x * 256 + threadIdx.x;  // 0..4095
    const int g  = blockIdx.y;                      // 0..13
    const int b  = blockIdx.z;                      // 0..7
    const int ho = p >> 6;
    const int wo = p & 63;

    const float* pgb = g_pg + (size_t)b * PGC * HWn;

    #pragma unroll
    for (int k = 0; k < 9; k++) {
        const float dy = pgb[(size_t)(g * 18 + 2 * k) * HWn + p];
        const float dx = pgb[(size_t)(g * 18 + 2 * k + 1) * HWn + p];
        const float mv = pgb[(size_t)(252 + g * 9 + k) * HWn + p];
        const float mask = 1.0f / (1.0f + __expf(-mv));

        const float yf = (float)(ho - 1 + k / 3) + dy;
        const float xf = (float)(wo - 1 + k % 3) + dx;
        const float y0f = floorf(yf);
        const float x0f = floorf(xf);
        const int y0 = (int)y0f;
        const int x0 = (int)x0f;
        const float wy1 = yf - y0f, wx1 = xf - x0f;
        const float wy0 = 1.f - wy1, wx0 = 1.f - wx1;

        const bool vy0 = (y0 >= 0)     && (y0 < Hn);
        const bool vy1 = (y0 + 1 >= 0) && (y0 + 1 < Hn);
        const bool vx0 = (x0 >= 0)     && (x0 < Wn);
        const bool vx1 = (x0 + 1 >= 0) && (x0 + 1 < Wn);

        const int y0c = min(max(y0, 0), Hn - 1);
        const int y1c = min(max(y0 + 1, 0), Hn - 1);
        const int x0c = min(max(x0, 0), Wn - 1);
        const int x1c = min(max(x0 + 1, 0), Wn - 1);

        const float w00 = (vy0 && vx0) ? wy0 * wx0 * mask : 0.f;
        const float w01 = (vy0 && vx1) ? wy0 * wx1 * mask : 0.f;
        const float w10 = (vy1 && vx0) ? wy1 * wx0 * mask : 0.f;
        const float w11 = (vy1 && vx1) ? wy1 * wx1 * mask : 0.f;

        const int i00 = y0c * Wn + x0c;
        const int i01 = y0c * Wn + x1c;
        const int i10 = y1c * Wn + x0c;
        const int i11 = y1c * Wn + x1c;

        #pragma unroll
        for (int cc = 0; cc < 8; cc++) {
            const float* img = x + ((size_t)b * Cn + g * 8 + cc) * HWn;
            const float v = img[i00] * w00 + img[i01] * w01
                          + img[i10] * w10 + img[i11] * w11;
            g_samp[((size_t)b * CKn + (size_t)(g * 8 + cc) * 9 + k) * HWn + p] = v;
        }
    }
}

// ---------------------------------------------------------------------------
// Kernel 3: out[b][o][p] = sum_ck W[o][ck] * samp[b][ck][p] + bias[o]
// v3: same 56x128x16 tiling but f32x2-packed: A pre-duplicated float2 in
// smem (LDS.64 bcast), B float4 -> 2 packs, 14 FFMA2 per k-step.
// Slots/FMA: 1.29 -> 0.86.
// ---------------------------------------------------------------------------
__global__ void __launch_bounds__(256) gemm_kernel(
    const float* __restrict__ w,      // (O, C, 3, 3) == (O, 1008) row-major
    const float* __restrict__ bias,
    float* __restrict__ out)
{
    __shared__ __align__(8)  float2 sW2[16][56];
    __shared__ __align__(16) float  sS[16][128];

    const int tid = threadIdx.x;
    const int tn  = tid & 31;     // pixel lane: 4 consecutive px each
    const int tm  = tid >> 5;     // row group (warp id): 7 rows each
    const int p0  = blockIdx.x * 128;
    const int m0  = blockIdx.y * 56;
    const int b   = blockIdx.z;

    const float* Sb = g_samp + (size_t)b * CKn * HWn;

    u64 acc2[7][2];
    #pragma unroll
    for (int j = 0; j < 7; j++) { acc2[j][0] = 0ull; acc2[j][1] = 0ull; }

    for (int k0 = 0; k0 < CKn; k0 += 16) {
        // A tile: 56x16, duplicated into float2
        for (int i = tid; i < 56 * 16; i += 256) {
            int m = i >> 4, kk = i & 15;
            float v = w[(size_t)(m0 + m) * CKn + k0 + kk];
            sW2[kk][m] = make_float2(v, v);
        }
        // B tile: 16x128 as float4 (512 float4 loads)
        for (int i = tid; i < 512; i += 256) {
            int kk = i >> 5;
            int pp = (i & 31) << 2;
            *(float4*)&sS[kk][pp] =
                *(const float4*)&Sb[(size_t)(k0 + kk) * HWn + p0 + pp];
        }
        __syncthreads();

        #pragma unroll
        for (int kk = 0; kk < 16; kk++) {
            u64 a2[7];
            #pragma unroll
            for (int j = 0; j < 7; j++)
                a2[j] = *(const u64*)&sW2[kk][tm * 7 + j];   // LDS.64 bcast
            const float4 bv = *(const float4*)&sS[kk][tn * 4];
            const u64 b01 = pack2(bv.x, bv.y);
            const u64 b23 = pack2(bv.z, bv.w);
            #pragma unroll
            for (int j = 0; j < 7; j++) {
                acc2[j][0] = ffma2(a2[j], b01, acc2[j][0]);
                acc2[j][1] = ffma2(a2[j], b23, acc2[j][1]);
            }
        }
        __syncthreads();
    }

    #pragma unroll
    for (int j = 0; j < 7; j++) {
        const int m = m0 + tm * 7 + j;
        const float bs = bias[m];
        const u64 bs2 = pack2(bs, bs);
        ulonglong2 st;
        st.x = add2(acc2[j][0], bs2);
        st.y = add2(acc2[j][1], bs2);
        *(ulonglong2*)&out[((size_t)b * On + m) * HWn + p0 + tn * 4] = st;
    }
}

// ---------------------------------------------------------------------------
extern "C" void kernel_launch(void* const* d_in, const int* in_sizes, int n_in,
                              void* d_out, int out_size)
{
    const float* x   = (const float*)d_in[0];   // (8,112,64,64)
    const float* pgw = (const float*)d_in[1];   // (378,112,3,3)
    const float* pgb = (const float*)d_in[2];   // (378,)
    const float* wt  = (const float*)d_in[3];   // (112,112,3,3)
    const float* bs  = (const float*)d_in[4];   // (112,)
    float* out = (float*)d_out;                 // (8,112,64,64)

    pg_conv_kernel<<<dim3(4, 42, 8), 256>>>(x, pgw, pgb);
    sample_kernel<<<dim3(16, 14, 8), 256>>>(x);
    gemm_kernel<<<dim3(32, 2, 8), 256>>>(wt, bs, out);
}